// round 1
// baseline (speedup 1.0000x reference)
#include <cuda_runtime.h>

#define F_FRAMES 64
#define N_PTS    4096
#define M_BOX    128
#define BLOCKS_PER_FRAME 8
#define PTS_PER_BLOCK    (N_PTS / BLOCKS_PER_FRAME)   // 512
#define THREADS  256
#define GRID     (F_FRAMES * BLOCKS_PER_FRAME)        // 512

// Persistent accumulators (zero-initialized at module load; the finishing
// block re-zeroes them every launch so graph replays are self-consistent).
__device__ float    g_sum[F_FRAMES];
__device__ int      g_cnt[F_FRAMES];
__device__ unsigned g_done;

__global__ __launch_bounds__(THREADS)
void calib_loss_kernel(const float* __restrict__ points,
                       const float* __restrict__ bboxes,
                       const int*   __restrict__ inL,
                       const int*   __restrict__ inR,
                       const float* __restrict__ quat,
                       const float* __restrict__ trans,
                       const float* __restrict__ K,
                       float*       __restrict__ out)
{
    __shared__ float2 sL[M_BOX];
    __shared__ float2 sPad;          // 8B pad: shifts sR banks vs sL (divergent-side LDS stays conflict-free)
    __shared__ float2 sR[M_BOX];
    __shared__ int    sAnyL, sAnyR;
    __shared__ float  warpSum[THREADS / 32];
    __shared__ int    warpCnt[THREADS / 32];

    const int tid = threadIdx.x;
    const int f   = blockIdx.x / BLOCKS_PER_FRAME;
    const int blk = blockIdx.x % BLOCKS_PER_FRAME;

    if (tid == 0) { sAnyL = 0; sAnyR = 0; sPad.x = 0.f; }
    __syncthreads();

    // ---- Build masked center tables for this frame ----
    for (int j = tid; j < M_BOX; j += THREADS) {
        const float* bb = bboxes + ((size_t)f * M_BOX + j) * 4;
        float cx = bb[0], cy = bb[1];
        int fl = inL[f * M_BOX + j];
        int fr = inR[f * M_BOX + j];
        sL[j] = (fl > 0) ? make_float2(cx, cy) : make_float2(1e18f, 1e18f);
        sR[j] = (fr > 0) ? make_float2(cx, cy) : make_float2(1e18f, 1e18f);
        if (fl > 0) atomicOr(&sAnyL, 1);
        if (fr > 0) atomicOr(&sAnyR, 1);
    }

    // ---- Fold projection: A = K@R (quaternion-normalized), b = K@t ----
    const float oqx = quat[0], oqy = quat[1], oqz = quat[2], oqw = quat[3];
    float qn = rsqrtf(oqx*oqx + oqy*oqy + oqz*oqz + oqw*oqw);
    float qx = oqx*qn, qy = oqy*qn, qz = oqz*qn, qw = oqw*qn;
    float R00 = 1.f - 2.f*(qy*qy + qz*qz), R01 = 2.f*(qx*qy - qz*qw), R02 = 2.f*(qx*qz + qy*qw);
    float R10 = 2.f*(qx*qy + qz*qw), R11 = 1.f - 2.f*(qx*qx + qz*qz), R12 = 2.f*(qy*qz - qx*qw);
    float R20 = 2.f*(qx*qz - qy*qw), R21 = 2.f*(qy*qz + qx*qw), R22 = 1.f - 2.f*(qx*qx + qy*qy);
    const float tx = trans[0], ty = trans[1], tz = trans[2];
    const float k00 = K[0], k01 = K[1], k02 = K[2];
    const float k10 = K[3], k11 = K[4], k12 = K[5];
    const float k20 = K[6], k21 = K[7], k22 = K[8];
    float a00 = k00*R00 + k01*R10 + k02*R20, a01 = k00*R01 + k01*R11 + k02*R21, a02 = k00*R02 + k01*R12 + k02*R22;
    float a10 = k10*R00 + k11*R10 + k12*R20, a11 = k10*R01 + k11*R11 + k12*R21, a12 = k10*R02 + k11*R12 + k12*R22;
    float a20 = k20*R00 + k21*R10 + k22*R20, a21 = k20*R01 + k21*R11 + k22*R21, a22 = k20*R02 + k21*R12 + k22*R22;
    float b0 = k00*tx + k01*ty + k02*tz;
    float b1 = k10*tx + k11*ty + k12*tz;
    float b2 = k20*tx + k21*ty + k22*tz;

    __syncthreads();

    const int anyL = sAnyL;
    const int anyR = sAnyR;

    // ---- Point loop (2 points/thread), branch-free box scan ----
    float accS = 0.f;
    int   accC = 0;
    for (int p = tid; p < PTS_PER_BLOCK; p += THREADS) {
        int n = blk * PTS_PER_BLOCK + p;
        const float* pt = points + ((size_t)f * N_PTS + n) * 5;
        float x = pt[0], y = pt[1], z = pt[2], vy = pt[4];

        const float2* cp;
        int pv;
        if (vy > 0.f)      { cp = sL; pv = anyL; }
        else if (vy < 0.f) { cp = sR; pv = anyR; }
        else               { cp = sL; pv = 0; }

        if (pv) {
            float w  = fmaf(a20, x, fmaf(a21, y, fmaf(a22, z, b2)));
            float iw = __fdividef(1.f, w);
            float u  = fmaf(a00, x, fmaf(a01, y, fmaf(a02, z, b0))) * iw;
            float v  = fmaf(a10, x, fmaf(a11, y, fmaf(a12, z, b1))) * iw;

            float d0 = 3.9e37f, d1 = 3.9e37f, d2m = 3.9e37f, d3 = 3.9e37f;
            #pragma unroll 8
            for (int j = 0; j < M_BOX; j += 4) {
                float2 c0 = cp[j+0]; float dx0 = u - c0.x, dy0 = v - c0.y;
                float2 c1 = cp[j+1]; float dx1 = u - c1.x, dy1 = v - c1.y;
                float2 c2 = cp[j+2]; float dx2 = u - c2.x, dy2 = v - c2.y;
                float2 c3 = cp[j+3]; float dx3 = u - c3.x, dy3 = v - c3.y;
                d0  = fminf(d0,  fmaf(dx0, dx0, dy0*dy0));
                d1  = fminf(d1,  fmaf(dx1, dx1, dy1*dy1));
                d2m = fminf(d2m, fmaf(dx2, dx2, dy2*dy2));
                d3  = fminf(d3,  fmaf(dx3, dx3, dy3*dy3));
            }
            float dmin2 = fminf(fminf(d0, d1), fminf(d2m, d3));
            float ds = sqrtf(dmin2);
            float h  = (ds <= 50.f) ? (0.5f * dmin2) : (50.f * (ds - 25.f));
            accS += h;
            accC += 1;
        }
    }

    // ---- Block reduction ----
    #pragma unroll
    for (int o = 16; o > 0; o >>= 1) {
        accS += __shfl_down_sync(0xffffffffu, accS, o);
        accC += __shfl_down_sync(0xffffffffu, accC, o);
    }
    const int wid = tid >> 5, lid = tid & 31;
    if (lid == 0) { warpSum[wid] = accS; warpCnt[wid] = accC; }
    __syncthreads();

    if (wid == 0) {
        float s = (lid < THREADS / 32) ? warpSum[lid] : 0.f;
        int   c = (lid < THREADS / 32) ? warpCnt[lid] : 0;
        #pragma unroll
        for (int o = 4; o > 0; o >>= 1) {
            s += __shfl_down_sync(0xffffffffu, s, o);
            c += __shfl_down_sync(0xffffffffu, c, o);
        }
        if (lid == 0) {
            if (c > 0) {
                atomicAdd(&g_sum[f], s);
                atomicAdd(&g_cnt[f], c);
            }
            __threadfence();
            unsigned t = atomicAdd(&g_done, 1u);
            if (t == (unsigned)(GRID - 1)) {
                // Last block: finish the scalar and reset state for next replay.
                float total = 0.f;
                int   nf = 0;
                #pragma unroll 8
                for (int ff = 0; ff < F_FRAMES; ff++) {
                    float ss = *((volatile float*)&g_sum[ff]);
                    int   cc = *((volatile int*)&g_cnt[ff]);
                    if (cc > 0) { total += ss / (float)cc; nf++; }
                    g_sum[ff] = 0.f;
                    g_cnt[ff] = 0;
                }
                float avg = (nf > 0) ? (total / (float)nf) : 0.f;
                float nrm = sqrtf(oqx*oqx + oqy*oqy + oqz*oqz + oqw*oqw);
                float dq  = 1.f - nrm;
                float reg = 0.01f * (tx*tx + ty*ty + tz*tz + dq*dq);
                out[0] = avg + reg;
                __threadfence();
                g_done = 0u;
            }
        }
    }
}

extern "C" void kernel_launch(void* const* d_in, const int* in_sizes, int n_in,
                              void* d_out, int out_size)
{
    const float* points = (const float*)d_in[0];
    const float* bboxes = (const float*)d_in[1];
    const int*   inL    = (const int*)  d_in[2];
    const int*   inR    = (const int*)  d_in[3];
    const float* quat   = (const float*)d_in[4];
    const float* trans  = (const float*)d_in[5];
    const float* K      = (const float*)d_in[6];
    float*       out    = (float*)d_out;
    (void)in_sizes; (void)n_in; (void)out_size;

    calib_loss_kernel<<<GRID, THREADS>>>(points, bboxes, inL, inR, quat, trans, K, out);
}

// round 2
// speedup vs baseline: 1.2529x; 1.2529x over previous
#include <cuda_runtime.h>

#define F_FRAMES 64
#define N_PTS    4096
#define M_BOX    128
#define BLOCKS_PER_FRAME 8
#define PTS_PER_BLOCK    (N_PTS / BLOCKS_PER_FRAME)   // 512
#define THREADS  128
#define GRID     (F_FRAMES * BLOCKS_PER_FRAME)        // 512

__device__ float    g_sum[F_FRAMES];
__device__ int      g_cnt[F_FRAMES];
__device__ unsigned g_done;

__device__ __forceinline__ float huber_of_d2(float d2) {
    float ds = sqrtf(d2);
    return (ds <= 50.f) ? (0.5f * d2) : (50.f * (ds - 25.f));
}

__global__ __launch_bounds__(THREADS)
void calib_loss_kernel(const float* __restrict__ points,
                       const float* __restrict__ bboxes,
                       const int*   __restrict__ inL,
                       const int*   __restrict__ inR,
                       const float* __restrict__ quat,
                       const float* __restrict__ trans,
                       const float* __restrict__ K,
                       float*       __restrict__ out)
{
    __shared__ float2 sCL[M_BOX];           // compacted valid left centers
    __shared__ float2 sCR[M_BOX];           // compacted valid right centers
    __shared__ float2 sPL[PTS_PER_BLOCK];   // (u,v) of left-valid points
    __shared__ float2 sPR[PTS_PER_BLOCK];   // (u,v) of right-valid points
    __shared__ int    nCL, nCR, nPL, nPR;
    __shared__ float  warpSum[THREADS / 32];
    __shared__ int    warpCnt[THREADS / 32];

    const int tid  = threadIdx.x;
    const int lane = tid & 31;
    const int wid  = tid >> 5;
    const int f    = blockIdx.x / BLOCKS_PER_FRAME;
    const int blk  = blockIdx.x % BLOCKS_PER_FRAME;

    if (tid == 0) { nCL = 0; nCR = 0; nPL = 0; nPR = 0; }
    __syncthreads();

    // ---- Compact valid centers (one box per thread; M_BOX == THREADS) ----
    {
        int j = tid;
        const float* bb = bboxes + ((size_t)f * M_BOX + j) * 4;
        float cx = bb[0], cy = bb[1];
        bool fl = inL[f * M_BOX + j] > 0;
        bool fr = inR[f * M_BOX + j] > 0;
        // warp-aggregated push: left
        unsigned ml = __ballot_sync(0xffffffffu, fl);
        if (ml) {
            int leader = __ffs(ml) - 1;
            int base = 0;
            if (lane == leader) base = atomicAdd(&nCL, __popc(ml));
            base = __shfl_sync(0xffffffffu, base, leader);
            if (fl) sCL[base + __popc(ml & ((1u << lane) - 1u))] = make_float2(cx, cy);
        }
        unsigned mr = __ballot_sync(0xffffffffu, fr);
        if (mr) {
            int leader = __ffs(mr) - 1;
            int base = 0;
            if (lane == leader) base = atomicAdd(&nCR, __popc(mr));
            base = __shfl_sync(0xffffffffu, base, leader);
            if (fr) sCR[base + __popc(mr & ((1u << lane) - 1u))] = make_float2(cx, cy);
        }
    }

    // ---- Fold projection: A = K@R (normalized quaternion), b = K@t ----
    const float oqx = quat[0], oqy = quat[1], oqz = quat[2], oqw = quat[3];
    float qn = rsqrtf(oqx*oqx + oqy*oqy + oqz*oqz + oqw*oqw);
    float qx = oqx*qn, qy = oqy*qn, qz = oqz*qn, qw = oqw*qn;
    float R00 = 1.f - 2.f*(qy*qy + qz*qz), R01 = 2.f*(qx*qy - qz*qw), R02 = 2.f*(qx*qz + qy*qw);
    float R10 = 2.f*(qx*qy + qz*qw), R11 = 1.f - 2.f*(qx*qx + qz*qz), R12 = 2.f*(qy*qz - qx*qw);
    float R20 = 2.f*(qx*qz - qy*qw), R21 = 2.f*(qy*qz + qx*qw), R22 = 1.f - 2.f*(qx*qx + qy*qy);
    const float tx = trans[0], ty = trans[1], tz = trans[2];
    const float k00 = K[0], k01 = K[1], k02 = K[2];
    const float k10 = K[3], k11 = K[4], k12 = K[5];
    const float k20 = K[6], k21 = K[7], k22 = K[8];
    float a00 = k00*R00 + k01*R10 + k02*R20, a01 = k00*R01 + k01*R11 + k02*R21, a02 = k00*R02 + k01*R12 + k02*R22;
    float a10 = k10*R00 + k11*R10 + k12*R20, a11 = k10*R01 + k11*R11 + k12*R21, a12 = k10*R02 + k11*R12 + k12*R22;
    float a20 = k20*R00 + k21*R10 + k22*R20, a21 = k20*R01 + k21*R11 + k22*R21, a22 = k20*R02 + k21*R12 + k22*R22;
    float b0 = k00*tx + k01*ty + k02*tz;
    float b1 = k10*tx + k11*ty + k12*tz;
    float b2 = k20*tx + k21*ty + k22*tz;

    __syncthreads();
    const bool anyL = (nCL > 0);
    const bool anyR = (nCR > 0);

    // ---- Project points, partition (u,v) by vy sign into shared lists ----
    #pragma unroll
    for (int k = 0; k < PTS_PER_BLOCK / THREADS; ++k) {
        int p = tid + k * THREADS;
        int n = blk * PTS_PER_BLOCK + p;
        const float* pt = points + ((size_t)f * N_PTS + n) * 5;
        float x = pt[0], y = pt[1], z = pt[2], vy = pt[4];

        float w  = fmaf(a20, x, fmaf(a21, y, fmaf(a22, z, b2)));
        float iw = __fdividef(1.f, w);
        float u  = fmaf(a00, x, fmaf(a01, y, fmaf(a02, z, b0))) * iw;
        float v  = fmaf(a10, x, fmaf(a11, y, fmaf(a12, z, b1))) * iw;

        bool goL = (vy > 0.f) && anyL;
        bool goR = (vy < 0.f) && anyR;

        unsigned ml = __ballot_sync(0xffffffffu, goL);
        if (ml) {
            int leader = __ffs(ml) - 1;
            int base = 0;
            if (lane == leader) base = atomicAdd(&nPL, __popc(ml));
            base = __shfl_sync(0xffffffffu, base, leader);
            if (goL) sPL[base + __popc(ml & ((1u << lane) - 1u))] = make_float2(u, v);
        }
        unsigned mr = __ballot_sync(0xffffffffu, goR);
        if (mr) {
            int leader = __ffs(mr) - 1;
            int base = 0;
            if (lane == leader) base = atomicAdd(&nPR, __popc(mr));
            base = __shfl_sync(0xffffffffu, base, leader);
            if (goR) sPR[base + __popc(mr & ((1u << lane) - 1u))] = make_float2(u, v);
        }
    }
    __syncthreads();

    // ---- Table passes: uniform-address broadcast loop, 2 points/thread ----
    float accS = 0.f;
    int   accC = 0;

    {
        const int npl = nPL, ncl = nCL;
        for (int base = 0; base + tid < npl; base += 2 * THREADS) {
            int i0 = base + tid, i1 = i0 + THREADS;
            bool h1 = (i1 < npl);
            float2 p0 = sPL[i0];
            float2 p1 = h1 ? sPL[i1] : p0;
            float d0 = 3.9e37f, d1 = 3.9e37f;
            #pragma unroll 4
            for (int j = 0; j < ncl; ++j) {
                float2 c = sCL[j];
                float dx0 = p0.x - c.x, dy0 = p0.y - c.y;
                d0 = fminf(d0, fmaf(dx0, dx0, dy0 * dy0));
                float dx1 = p1.x - c.x, dy1 = p1.y - c.y;
                d1 = fminf(d1, fmaf(dx1, dx1, dy1 * dy1));
            }
            accS += huber_of_d2(d0); accC++;
            if (h1) { accS += huber_of_d2(d1); accC++; }
        }
    }
    {
        const int npr = nPR, ncr = nCR;
        for (int base = 0; base + tid < npr; base += 2 * THREADS) {
            int i0 = base + tid, i1 = i0 + THREADS;
            bool h1 = (i1 < npr);
            float2 p0 = sPR[i0];
            float2 p1 = h1 ? sPR[i1] : p0;
            float d0 = 3.9e37f, d1 = 3.9e37f;
            #pragma unroll 4
            for (int j = 0; j < ncr; ++j) {
                float2 c = sCR[j];
                float dx0 = p0.x - c.x, dy0 = p0.y - c.y;
                d0 = fminf(d0, fmaf(dx0, dx0, dy0 * dy0));
                float dx1 = p1.x - c.x, dy1 = p1.y - c.y;
                d1 = fminf(d1, fmaf(dx1, dx1, dy1 * dy1));
            }
            accS += huber_of_d2(d0); accC++;
            if (h1) { accS += huber_of_d2(d1); accC++; }
        }
    }

    // ---- Block reduction ----
    #pragma unroll
    for (int o = 16; o > 0; o >>= 1) {
        accS += __shfl_down_sync(0xffffffffu, accS, o);
        accC += __shfl_down_sync(0xffffffffu, accC, o);
    }
    if (lane == 0) { warpSum[wid] = accS; warpCnt[wid] = accC; }
    __syncthreads();

    if (wid == 0) {
        float s = (lane < THREADS / 32) ? warpSum[lane] : 0.f;
        int   c = (lane < THREADS / 32) ? warpCnt[lane] : 0;
        #pragma unroll
        for (int o = 2; o > 0; o >>= 1) {
            s += __shfl_down_sync(0xffffffffu, s, o);
            c += __shfl_down_sync(0xffffffffu, c, o);
        }
        if (lane == 0) {
            if (c > 0) {
                atomicAdd(&g_sum[f], s);
                atomicAdd(&g_cnt[f], c);
            }
            __threadfence();
            unsigned t = atomicAdd(&g_done, 1u);
            if (t == (unsigned)(GRID - 1)) {
                float total = 0.f;
                int   nf = 0;
                #pragma unroll 8
                for (int ff = 0; ff < F_FRAMES; ff++) {
                    float ss = *((volatile float*)&g_sum[ff]);
                    int   cc = *((volatile int*)&g_cnt[ff]);
                    if (cc > 0) { total += ss / (float)cc; nf++; }
                    g_sum[ff] = 0.f;
                    g_cnt[ff] = 0;
                }
                float avg = (nf > 0) ? (total / (float)nf) : 0.f;
                float nrm = sqrtf(oqx*oqx + oqy*oqy + oqz*oqz + oqw*oqw);
                float dq  = 1.f - nrm;
                float reg = 0.01f * (tx*tx + ty*ty + tz*tz + dq*dq);
                out[0] = avg + reg;
                __threadfence();
                g_done = 0u;
            }
        }
    }
}

extern "C" void kernel_launch(void* const* d_in, const int* in_sizes, int n_in,
                              void* d_out, int out_size)
{
    const float* points = (const float*)d_in[0];
    const float* bboxes = (const float*)d_in[1];
    const int*   inL    = (const int*)  d_in[2];
    const int*   inR    = (const int*)  d_in[3];
    const float* quat   = (const float*)d_in[4];
    const float* trans  = (const float*)d_in[5];
    const float* K      = (const float*)d_in[6];
    float*       out    = (float*)d_out;
    (void)in_sizes; (void)n_in; (void)out_size;

    calib_loss_kernel<<<GRID, THREADS>>>(points, bboxes, inL, inR, quat, trans, K, out);
}

// round 3
// speedup vs baseline: 1.3040x; 1.0407x over previous
#include <cuda_runtime.h>

#define F_FRAMES 64
#define N_PTS    4096
#define M_BOX    128
#define BLOCKS_PER_FRAME 16
#define PTS_PER_BLOCK    (N_PTS / BLOCKS_PER_FRAME)   // 256
#define THREADS  256
#define GRID     (F_FRAMES * BLOCKS_PER_FRAME)        // 1024

__device__ float    g_sum[F_FRAMES];
__device__ int      g_cnt[F_FRAMES];
__device__ unsigned g_done;

__global__ __launch_bounds__(THREADS)
void calib_loss_kernel(const float* __restrict__ points,
                       const float* __restrict__ bboxes,
                       const int*   __restrict__ inL,
                       const int*   __restrict__ inR,
                       const float* __restrict__ quat,
                       const float* __restrict__ trans,
                       const float* __restrict__ K,
                       float*       __restrict__ out)
{
    __shared__ float2 sCL[M_BOX + 4];   // compacted valid left centers (+sentinel pad)
    __shared__ float2 sCR[M_BOX + 4];   // compacted valid right centers (+sentinel pad)
    __shared__ int    nCL, nCR;
    __shared__ float  warpSum[THREADS / 32];
    __shared__ int    warpCnt[THREADS / 32];

    const int tid  = threadIdx.x;
    const int lane = tid & 31;
    const int wid  = tid >> 5;
    const int f    = blockIdx.x / BLOCKS_PER_FRAME;
    const int blk  = blockIdx.x % BLOCKS_PER_FRAME;

    if (tid == 0) { nCL = 0; nCR = 0; }
    __syncthreads();

    // ---- Compact valid centers (threads 0..127, one box each) ----
    if (tid < M_BOX) {
        int j = tid;
        const float* bb = bboxes + ((size_t)f * M_BOX + j) * 4;
        float cx = bb[0], cy = bb[1];
        bool fl = inL[f * M_BOX + j] > 0;
        bool fr = inR[f * M_BOX + j] > 0;
        unsigned ml = __ballot_sync(0xffffffffu, fl);
        if (ml) {
            int leader = __ffs(ml) - 1;
            int base = 0;
            if (lane == leader) base = atomicAdd(&nCL, __popc(ml));
            base = __shfl_sync(0xffffffffu, base, leader);
            if (fl) sCL[base + __popc(ml & ((1u << lane) - 1u))] = make_float2(cx, cy);
        }
        unsigned mr = __ballot_sync(0xffffffffu, fr);
        if (mr) {
            int leader = __ffs(mr) - 1;
            int base = 0;
            if (lane == leader) base = atomicAdd(&nCR, __popc(mr));
            base = __shfl_sync(0xffffffffu, base, leader);
            if (fr) sCR[base + __popc(mr & ((1u << lane) - 1u))] = make_float2(cx, cy);
        }
    }

    // ---- Fold projection: A = K@R (normalized quaternion), b = K@t ----
    const float oqx = quat[0], oqy = quat[1], oqz = quat[2], oqw = quat[3];
    float qn = rsqrtf(oqx*oqx + oqy*oqy + oqz*oqz + oqw*oqw);
    float qx = oqx*qn, qy = oqy*qn, qz = oqz*qn, qw = oqw*qn;
    float R00 = 1.f - 2.f*(qy*qy + qz*qz), R01 = 2.f*(qx*qy - qz*qw), R02 = 2.f*(qx*qz + qy*qw);
    float R10 = 2.f*(qx*qy + qz*qw), R11 = 1.f - 2.f*(qx*qx + qz*qz), R12 = 2.f*(qy*qz - qx*qw);
    float R20 = 2.f*(qx*qz - qy*qw), R21 = 2.f*(qy*qz + qx*qw), R22 = 1.f - 2.f*(qx*qx + qy*qy);
    const float tx = trans[0], ty = trans[1], tz = trans[2];
    const float k00 = K[0], k01 = K[1], k02 = K[2];
    const float k10 = K[3], k11 = K[4], k12 = K[5];
    const float k20 = K[6], k21 = K[7], k22 = K[8];
    float a00 = k00*R00 + k01*R10 + k02*R20, a01 = k00*R01 + k01*R11 + k02*R21, a02 = k00*R02 + k01*R12 + k02*R22;
    float a10 = k10*R00 + k11*R10 + k12*R20, a11 = k10*R01 + k11*R11 + k12*R21, a12 = k10*R02 + k11*R12 + k12*R22;
    float a20 = k20*R00 + k21*R10 + k22*R20, a21 = k20*R01 + k21*R11 + k22*R21, a22 = k20*R02 + k21*R12 + k22*R22;
    float b0 = k00*tx + k01*ty + k02*tz;
    float b1 = k10*tx + k11*ty + k12*tz;
    float b2 = k20*tx + k21*ty + k22*tz;

    __syncthreads();

    // ---- Sentinel-pad both lists to a multiple of 4 ----
    if (tid < 4) {
        sCL[nCL + tid] = make_float2(1e18f, 1e18f);
        sCR[nCR + tid] = make_float2(1e18f, 1e18f);
    }
    __syncthreads();

    const int cntL = nCL, cntR = nCR;

    // ---- One point per thread ----
    float accS = 0.f;
    int   accC = 0;
    {
        int n = blk * PTS_PER_BLOCK + tid;
        const float* pt = points + ((size_t)f * N_PTS + n) * 5;
        float x  = pt[0], y = pt[1], z = pt[2], vy = pt[4];

        const float2* cp = (vy > 0.f) ? sCL : sCR;
        int nc           = (vy > 0.f) ? cntL : cntR;
        bool pv = ((vy > 0.f) && (cntL > 0)) || ((vy < 0.f) && (cntR > 0));

        if (pv) {
            float w  = fmaf(a20, x, fmaf(a21, y, fmaf(a22, z, b2)));
            float iw = __fdividef(1.f, w);
            float u  = fmaf(a00, x, fmaf(a01, y, fmaf(a02, z, b0))) * iw;
            float v  = fmaf(a10, x, fmaf(a11, y, fmaf(a12, z, b1))) * iw;

            int ncr4 = (nc + 3) & ~3;   // sentinel pad makes overrun safe
            float d0 = 3.9e37f, d1 = 3.9e37f, d2 = 3.9e37f, d3 = 3.9e37f;
            for (int j = 0; j < ncr4; j += 4) {
                float2 c0 = cp[j+0]; float dx0 = u - c0.x, dy0 = v - c0.y;
                float2 c1 = cp[j+1]; float dx1 = u - c1.x, dy1 = v - c1.y;
                float2 c2 = cp[j+2]; float dx2 = u - c2.x, dy2 = v - c2.y;
                float2 c3 = cp[j+3]; float dx3 = u - c3.x, dy3 = v - c3.y;
                d0 = fminf(d0, fmaf(dx0, dx0, dy0 * dy0));
                d1 = fminf(d1, fmaf(dx1, dx1, dy1 * dy1));
                d2 = fminf(d2, fmaf(dx2, dx2, dy2 * dy2));
                d3 = fminf(d3, fmaf(dx3, dx3, dy3 * dy3));
            }
            float dmin2 = fminf(fminf(d0, d1), fminf(d2, d3));
            float ds = sqrtf(dmin2);
            accS = (ds <= 50.f) ? (0.5f * dmin2) : (50.f * (ds - 25.f));
            accC = 1;
        }
    }

    // ---- Block reduction ----
    #pragma unroll
    for (int o = 16; o > 0; o >>= 1) {
        accS += __shfl_down_sync(0xffffffffu, accS, o);
        accC += __shfl_down_sync(0xffffffffu, accC, o);
    }
    if (lane == 0) { warpSum[wid] = accS; warpCnt[wid] = accC; }
    __syncthreads();

    if (wid == 0) {
        float s = (lane < THREADS / 32) ? warpSum[lane] : 0.f;
        int   c = (lane < THREADS / 32) ? warpCnt[lane] : 0;
        #pragma unroll
        for (int o = 4; o > 0; o >>= 1) {
            s += __shfl_down_sync(0xffffffffu, s, o);
            c += __shfl_down_sync(0xffffffffu, c, o);
        }
        if (lane == 0) {
            if (c > 0) {
                atomicAdd(&g_sum[f], s);
                atomicAdd(&g_cnt[f], c);
            }
            __threadfence();
            unsigned t = atomicAdd(&g_done, 1u);
            if (t == (unsigned)(GRID - 1)) {
                float total = 0.f;
                int   nf = 0;
                #pragma unroll 8
                for (int ff = 0; ff < F_FRAMES; ff++) {
                    float ss = *((volatile float*)&g_sum[ff]);
                    int   cc = *((volatile int*)&g_cnt[ff]);
                    if (cc > 0) { total += ss / (float)cc; nf++; }
                    g_sum[ff] = 0.f;
                    g_cnt[ff] = 0;
                }
                float avg = (nf > 0) ? (total / (float)nf) : 0.f;
                float nrm = sqrtf(oqx*oqx + oqy*oqy + oqz*oqz + oqw*oqw);
                float dq  = 1.f - nrm;
                float reg = 0.01f * (tx*tx + ty*ty + tz*tz + dq*dq);
                out[0] = avg + reg;
                __threadfence();
                g_done = 0u;
            }
        }
    }
}

extern "C" void kernel_launch(void* const* d_in, const int* in_sizes, int n_in,
                              void* d_out, int out_size)
{
    const float* points = (const float*)d_in[0];
    const float* bboxes = (const float*)d_in[1];
    const int*   inL    = (const int*)  d_in[2];
    const int*   inR    = (const int*)  d_in[3];
    const float* quat   = (const float*)d_in[4];
    const float* trans  = (const float*)d_in[5];
    const float* K      = (const float*)d_in[6];
    float*       out    = (float*)d_out;
    (void)in_sizes; (void)n_in; (void)out_size;

    calib_loss_kernel<<<GRID, THREADS>>>(points, bboxes, inL, inR, quat, trans, K, out);
}